// round 17
// baseline (speedup 1.0000x reference)
#include <cuda_runtime.h>
#include <cstdint>

// B=256, T=64 (K), S=16, U=4 -> P=256 pixels, O=1024 outputs/pixel.
//
// R16 architecture (persistent-pixel CTA), R17 fixes the W-prefetch sizing
// bug (6 float4/thread -> 4; pass = 128 o x 64 k = 2048 float4s exactly).
// A staged ONCE per CTA (64 KB); W streamed in 8 double-buffered passes
// (LDG->regs before the k-loop, STS after); epilogue per pass.
//
// kernel 1: transpose x -> g_xT32[p][t][b]
// kernel 2: grid 256 (p), block 512 = 32 tb (8 b) x 16 to (8 o).
//           Per pass: C[256 b x 128 o] += A[256x64] @ W[128x64]^T.
//           FFMA2 b-pair tile 8x8, acc2[4][8]; Wp 48B-group layout.

__device__ float g_xT32[256 * 64 * 256];  // [p][t][b], 16 MB

__device__ __forceinline__ uint32_t smem_u32(const void* p) {
    uint32_t a;
    asm("{ .reg .u64 t; cvta.to.shared.u64 t, %1; cvt.u32.u64 %0, t; }" : "=r"(a) : "l"(p));
    return a;
}
__device__ __forceinline__ void cp16(uint32_t sdst, const void* g) {
    asm volatile("cp.async.cg.shared.global [%0], [%1], 16;" :: "r"(sdst), "l"(g));
}
__device__ __forceinline__ unsigned long long dupf2(float v) {
    unsigned long long r;
    asm("mov.b64 %0, {%1, %1};" : "=l"(r) : "f"(v));
    return r;
}
__device__ __forceinline__ float2 unpackf2(unsigned long long v) {
    float2 r;
    asm("mov.b64 {%0, %1}, %2;" : "=f"(r.x), "=f"(r.y) : "l"(v));
    return r;
}

// ---------------------------------------------------------------------------
// Transpose: x[b][t][p] -> g_xT32[p*16384 + t*256 + b]
// ---------------------------------------------------------------------------
__global__ void transpose32_kernel(const float* __restrict__ x) {
    __shared__ float tile[32][33];
    int p0 = blockIdx.x * 32, b0 = blockIdx.y * 32, t = blockIdx.z;
    int tx = threadIdx.x, ty = threadIdx.y;
#pragma unroll
    for (int k = 0; k < 4; k++) {
        int br = ty + k * 8;
        tile[br][tx] = x[(size_t)(b0 + br) * 16384 + (size_t)t * 256 + p0 + tx];
    }
    __syncthreads();
#pragma unroll
    for (int k = 0; k < 4; k++) {
        int pr = ty + k * 8;
        g_xT32[(size_t)(p0 + pr) * 16384 + (size_t)t * 256 + b0 + tx] = tile[tx][pr];
    }
}

// ---------------------------------------------------------------------------
// GEMM. Wp row: 16 groups of 8 o (offsets (o>>3)*12 + (o&7)), 192 floats/row.
// ---------------------------------------------------------------------------
#define WROW 192
#define AS_F (64 * 256)              // 64 KB
#define WB_F (64 * WROW)             // one W buffer (padded): 48 KB
#define SMEM_BYTES ((AS_F + 2 * WB_F + 1024 + 64) * 4)   // ~168 KB

__global__ __launch_bounds__(512, 1) void gemm_kernel(const float* __restrict__ Wg_all,
                                                      const float* __restrict__ bias,
                                                      float* __restrict__ out) {
    extern __shared__ float smem[];
    float* As = smem;                         // [64 k][256 b]
    float* Wb = smem + AS_F;                  // [2][64 k][WROW]
    float* bias_s = smem + AS_F + 2 * WB_F;   // [1024]

    const int p  = blockIdx.x;
    const int tid = threadIdx.x;
    const int tb = tid >> 4;     // 0..31: b rows tb*8 .. tb*8+7
    const int to = tid & 15;     // 0..15: o (within pass) = to*8 + j

    const float* Wg = Wg_all + ((size_t)p << 16);

    // Prefetch W pass 0 into regs: 2048 float4s = 4 per thread
    float4 wreg[4];
#pragma unroll
    for (int j = 0; j < 4; j++)
        wreg[j] = __ldg((const float4*)(Wg) + tid + j * 512);

    // A: 64 KB cp.async; bias: 4 KB
    const float* Ag = g_xT32 + ((size_t)p << 14);
    uint32_t sA = smem_u32(As);
#pragma unroll
    for (int i = 0; i < 8; i++) {
        int idx = tid + i * 512;              // 4096 chunks of 16B
        cp16(sA + idx * 16, Ag + idx * 4);
    }
    if (tid < 256) cp16(smem_u32(bias_s) + tid * 16, bias + (size_t)p * 1024 + tid * 4);
    asm volatile("cp.async.commit_group;");

    // STS W0 -> buf 0
    {
        float* W0 = Wb;
#pragma unroll
        for (int j = 0; j < 4; j++) {
            int idx = tid + j * 512;          // 0..2047
            int o = idx >> 4;                 // 0..127
            int kc = (idx & 15) << 2;         // 0..60
            int od = ((o >> 3) * 12) + (o & 7);
            W0[(kc + 0) * WROW + od] = wreg[j].x;
            W0[(kc + 1) * WROW + od] = wreg[j].y;
            W0[(kc + 2) * WROW + od] = wreg[j].z;
            W0[(kc + 3) * WROW + od] = wreg[j].w;
        }
    }
    asm volatile("cp.async.wait_group 0;");
    __syncthreads();

    const int i4 = (p >> 4) << 2, j4 = (p & 15) << 2;
    const float* Abase = As + tb * 8;

#pragma unroll 1
    for (int pass = 0; pass < 8; pass++) {
        // Prefetch next pass's W into regs (consumed after k-loop)
        if (pass < 7) {
#pragma unroll
            for (int j = 0; j < 4; j++)
                wreg[j] = __ldg((const float4*)(Wg + (size_t)(pass + 1) * 8192) + tid + j * 512);
        }

        unsigned long long acc2[4][8];
#pragma unroll
        for (int i = 0; i < 4; i++)
#pragma unroll
            for (int j = 0; j < 8; j++) acc2[i][j] = 0ull;

        const float* Bbase = Wb + (pass & 1) * WB_F + to * 12;

#pragma unroll 16
        for (int k = 0; k < 64; k++) {
            ulonglong2 A0 = *(const ulonglong2*)(Abase + k * 256);
            ulonglong2 A1 = *(const ulonglong2*)(Abase + k * 256 + 4);
            unsigned long long a2[4] = {A0.x, A0.y, A1.x, A1.y};
            float4 B0 = *(const float4*)(Bbase + k * WROW);
            float4 B1 = *(const float4*)(Bbase + k * WROW + 4);
            unsigned long long bd[8];
            bd[0] = dupf2(B0.x); bd[1] = dupf2(B0.y);
            bd[2] = dupf2(B0.z); bd[3] = dupf2(B0.w);
            bd[4] = dupf2(B1.x); bd[5] = dupf2(B1.y);
            bd[6] = dupf2(B1.z); bd[7] = dupf2(B1.w);
#pragma unroll
            for (int i = 0; i < 4; i++)
#pragma unroll
                for (int j = 0; j < 8; j++) {
                    asm("fma.rn.f32x2 %0, %1, %2, %0;"
                        : "+l"(acc2[i][j]) : "l"(a2[i]), "l"(bd[j]));
                }
        }

        // STS next W into the other buffer (idle this pass)
        if (pass < 7) {
            float* Wn = Wb + ((pass + 1) & 1) * WB_F;
#pragma unroll
            for (int j = 0; j < 4; j++) {
                int idx = tid + j * 512;
                int o = idx >> 4;
                int kc = (idx & 15) << 2;
                int od = ((o >> 3) * 12) + (o & 7);
                Wn[(kc + 0) * WROW + od] = wreg[j].x;
                Wn[(kc + 1) * WROW + od] = wreg[j].y;
                Wn[(kc + 2) * WROW + od] = wreg[j].z;
                Wn[(kc + 3) * WROW + od] = wreg[j].w;
            }
        }

        // Epilogue for this pass: o0 = pass*128 + to*8
        int o0 = pass * 128 + to * 8;
        int t  = o0 >> 4;
        int ui = (o0 >> 2) & 3;               // 0 or 2
        int coloff0 = t * 4096 + (i4 + ui) * 64 + j4;
        int coloff1 = coloff0 + 64;           // ui+1
        float4 bv0 = *(const float4*)&bias_s[o0];
        float4 bv1 = *(const float4*)&bias_s[o0 + 4];
#pragma unroll
        for (int i = 0; i < 4; i++) {
            float2 c[8];
#pragma unroll
            for (int j = 0; j < 8; j++) c[j] = unpackf2(acc2[i][j]);
            size_t r0 = (size_t)(tb * 8 + 2 * i) * 262144;
            size_t r1 = r0 + 262144;
            *(float4*)(out + r0 + coloff0) =
                make_float4(c[0].x + bv0.x, c[1].x + bv0.y, c[2].x + bv0.z, c[3].x + bv0.w);
            *(float4*)(out + r0 + coloff1) =
                make_float4(c[4].x + bv1.x, c[5].x + bv1.y, c[6].x + bv1.z, c[7].x + bv1.w);
            *(float4*)(out + r1 + coloff0) =
                make_float4(c[0].y + bv0.x, c[1].y + bv0.y, c[2].y + bv0.z, c[3].y + bv0.w);
            *(float4*)(out + r1 + coloff1) =
                make_float4(c[4].y + bv1.x, c[5].y + bv1.y, c[6].y + bv1.z, c[7].y + bv1.w);
        }

        __syncthreads();   // next-W STS visible; all reads of old buffer done
    }
}

extern "C" void kernel_launch(void* const* d_in, const int* in_sizes, int n_in,
                              void* d_out, int out_size) {
    const float* x = (const float*)d_in[0];   // (256, 64, 16, 16)
    const float* W = (const float*)d_in[1];   // (256, 1024, 64)
    const float* b = (const float*)d_in[2];   // (256, 1024)
    float* out = (float*)d_out;               // (256, 64, 64, 64)
    (void)in_sizes; (void)n_in; (void)out_size;

    cudaFuncSetAttribute(gemm_kernel, cudaFuncAttributeMaxDynamicSharedMemorySize, SMEM_BYTES);

    transpose32_kernel<<<dim3(8, 8, 64), dim3(32, 8)>>>(x);
    gemm_kernel<<<256, 512, SMEM_BYTES>>>(W, b, out);
}